// round 16
// baseline (speedup 1.0000x reference)
#include <cuda_runtime.h>
#include <cuda_bf16.h>
#include <cuda_fp16.h>
#include <cstdint>
#include <math.h>

#define NN      2048
#define DIM     512
#define EDGE    8
#define GROWS   (EDGE * NN)
#define SLOTS   128
#define NSTEPS  5

// ---------------- device scratch (no allocation allowed) -------------------
__device__ __align__(256) float d_h [NN * DIM];
__device__ __align__(256) float d_z [NN * DIM];
__device__ __align__(256) __half d_t [NN * 4096];   // t = h @ [W_0..W_7], fp16
__device__ __align__(256) __nv_bfloat16 d_hh [NN * DIM], d_hl [NN * DIM];
__device__ __align__(256) __nv_bfloat16 d_ah [NN * DIM], d_al [NN * DIM];
__device__ __align__(256) __nv_bfloat16 d_rhh[NN * DIM], d_rhl[NN * DIM];
__device__ __align__(256) __nv_bfloat16 d_Bagg_h[4096 * DIM], d_Bagg_l[4096 * DIM]; // [n=4096][k=512]
__device__ __align__(256) __nv_bfloat16 d_Bzr_h[1024 * 1024], d_Bzr_l[1024 * 1024]; // [1024][1024]
__device__ __align__(256) __nv_bfloat16 d_Bh_h [DIM * 1024],  d_Bh_l [DIM * 1024];  // [512][1024]
__device__ int   d_cnt   [GROWS];
__device__ float d_cntf  [GROWS];
__device__ int   d_colidx_pad[GROWS * SLOTS];

// ---------------- PDL + mma/ldmatrix/cp.async helpers ----------------------
#define GDC_LAUNCH() asm volatile("griddepcontrol.launch_dependents;")
#define GDC_WAIT()   asm volatile("griddepcontrol.wait;" ::: "memory")

__device__ __forceinline__ void ldsm4(uint32_t* r, uint32_t addr) {
    asm volatile("ldmatrix.sync.aligned.m8n8.x4.shared.b16 {%0,%1,%2,%3}, [%4];"
        : "=r"(r[0]), "=r"(r[1]), "=r"(r[2]), "=r"(r[3]) : "r"(addr));
}
__device__ __forceinline__ void mma16816(float* d, const uint32_t* a, const uint32_t* b) {
    asm volatile("mma.sync.aligned.m16n8k16.row.col.f32.bf16.bf16.f32 "
        "{%0,%1,%2,%3}, {%4,%5,%6,%7}, {%8,%9}, {%0,%1,%2,%3};"
        : "+f"(d[0]), "+f"(d[1]), "+f"(d[2]), "+f"(d[3])
        : "r"(a[0]), "r"(a[1]), "r"(a[2]), "r"(a[3]), "r"(b[0]), "r"(b[1]));
}
__device__ __forceinline__ void cpa16(uint32_t smaddr, const void* g) {
    asm volatile("cp.async.cg.shared.global [%0], [%1], 16;" :: "r"(smaddr), "l"(g));
}
#define CPA_COMMIT() asm volatile("cp.async.commit_group;")
#define CPA_WAIT1()  asm volatile("cp.async.wait_group 1;")

__device__ __forceinline__ void store_hilo2(__nv_bfloat16* ph, __nv_bfloat16* pl,
                                            float v0, float v1) {
    __nv_bfloat16 h0 = __float2bfloat16(v0);
    __nv_bfloat16 h1 = __float2bfloat16(v1);
    __nv_bfloat16 l0 = __float2bfloat16(v0 - __bfloat162float(h0));
    __nv_bfloat16 l1 = __float2bfloat16(v1 - __bfloat162float(h1));
    *(__nv_bfloat162*)ph = __nv_bfloat162(h0, h1);
    *(__nv_bfloat162*)pl = __nv_bfloat162(l0, l1);
}

// ---------------- single-pass padded CSR build ------------------------------
__global__ void csr_build(const float* __restrict__ adj) {
    int warp = (blockIdx.x * blockDim.x + threadIdx.x) >> 5;
    int lane = threadIdx.x & 31;
    if (warp >= GROWS) return;
    int e = warp >> 11, n = warp & 2047;
    const float* base = adj + (size_t)n * 16384 + (size_t)e * 2048;
    int* dst = d_colidx_pad + (size_t)warp * SLOTS;
    int w = 0;
    for (int i0 = 0; i0 < 2048; i0 += 32) {
        float v = base[i0 + lane];
        unsigned b = __ballot_sync(0xffffffffu, v != 0.0f);
        if (v != 0.0f) {
            int pos = w + __popc(b & ((1u << lane) - 1u));
            if (pos < SLOTS) dst[pos] = i0 + lane;
        }
        w += __popc(b);
    }
    if (lane == 0) {
        d_cnt[warp] = (w < SLOTS) ? w : SLOTS;
        d_cntf[warp] = (float)w;
    }
}

// ---------------- init h + hi/lo -------------------------------------------
__global__ void init_h(const float* __restrict__ ann) {
    int idx = blockIdx.x * blockDim.x + threadIdx.x;
    if (idx >= NN * DIM) return;
    int n = idx >> 9, d = idx & 511;
    float v = (d < 256) ? ann[n * 256 + d] : 0.0f;
    d_h[idx] = v;
    __nv_bfloat16 h = __float2bfloat16(v);
    d_hh[idx] = h;
    d_hl[idx] = __float2bfloat16(v - __bfloat162float(h));
}

// ---------------- weight transpose+pack (14 jobs, one launch) --------------
__global__ void packAll(const float* __restrict__ Wp, const float* __restrict__ Wz,
                        const float* __restrict__ Uz, const float* __restrict__ Wr,
                        const float* __restrict__ Ur, const float* __restrict__ Wh,
                        const float* __restrict__ Uh) {
    __shared__ float t[32][33];
    const int job = blockIdx.z;
    const float* src;
    __nv_bfloat16 *dh, *dl;
    int Kstride, nofs, kofs;
    if (job < 8) {
        src = Wp + (size_t)job * DIM * DIM;
        dh = d_Bagg_h; dl = d_Bagg_l; Kstride = 512; nofs = job * 512; kofs = 0;
    } else if (job < 12) {
        dh = d_Bzr_h; dl = d_Bzr_l; Kstride = 1024;
        if (job == 8)       { src = Wz; nofs = 0;   kofs = 0;   }
        else if (job == 9)  { src = Uz; nofs = 0;   kofs = 512; }
        else if (job == 10) { src = Wr; nofs = 512; kofs = 0;   }
        else                { src = Ur; nofs = 512; kofs = 512; }
    } else {
        dh = d_Bh_h; dl = d_Bh_l; Kstride = 1024;
        if (job == 12) { src = Wh; nofs = 0; kofs = 0;   }
        else           { src = Uh; nofs = 0; kofs = 512; }
    }
    int k0 = blockIdx.x * 32, n0 = blockIdx.y * 32;
    int tx = threadIdx.x, ty = threadIdx.y;   // (32,8)
    #pragma unroll
    for (int j = 0; j < 32; j += 8)
        t[ty + j][tx] = src[(size_t)(k0 + ty + j) * DIM + n0 + tx];
    __syncthreads();
    #pragma unroll
    for (int j = 0; j < 32; j += 8) {
        float v = t[tx][ty + j];
        size_t o = (size_t)(nofs + n0 + ty + j) * Kstride + kofs + k0 + tx;
        __nv_bfloat16 h = __float2bfloat16(v);
        dh[o] = h;
        dl[o] = __float2bfloat16(v - __bfloat162float(h));
    }
}

// ---------------- fused gather-accumulate: a[n] = sum_e sum_m t_e[m] + cnt*b
__global__ void __launch_bounds__(128)
gather_acc(const float* __restrict__ bp) {
    GDC_LAUNCH();
    const int n = blockIdx.x;
    const int c = threadIdx.x;                 // 4 dims per thread
    GDC_WAIT();
    float4 acc = make_float4(0.f, 0.f, 0.f, 0.f);
    #pragma unroll 1
    for (int e = 0; e < EDGE; e++) {
        const int g = e * NN + n;
        const int* idxp = d_colidx_pad + (size_t)g * SLOTS;
        const int cnt = d_cnt[g];
        const __half* tb = d_t + e * 512 + c * 4;
        int j = 0;
        for (; j + 3 < cnt; j += 4) {
            int4 m4 = *(const int4*)(idxp + j);
            uint2 u0 = *(const uint2*)(tb + (size_t)m4.x * 4096);
            uint2 u1 = *(const uint2*)(tb + (size_t)m4.y * 4096);
            uint2 u2 = *(const uint2*)(tb + (size_t)m4.z * 4096);
            uint2 u3 = *(const uint2*)(tb + (size_t)m4.w * 4096);
            float2 a0 = __half22float2(*(__half2*)&u0.x), b0 = __half22float2(*(__half2*)&u0.y);
            float2 a1 = __half22float2(*(__half2*)&u1.x), b1 = __half22float2(*(__half2*)&u1.y);
            float2 a2 = __half22float2(*(__half2*)&u2.x), b2 = __half22float2(*(__half2*)&u2.y);
            float2 a3 = __half22float2(*(__half2*)&u3.x), b3 = __half22float2(*(__half2*)&u3.y);
            acc.x += (a0.x + a1.x) + (a2.x + a3.x);
            acc.y += (a0.y + a1.y) + (a2.y + a3.y);
            acc.z += (b0.x + b1.x) + (b2.x + b3.x);
            acc.w += (b0.y + b1.y) + (b2.y + b3.y);
        }
        for (; j < cnt; j++) {
            int m = __ldg(idxp + j);
            uint2 u = *(const uint2*)(tb + (size_t)m * 4096);
            float2 a = __half22float2(*(__half2*)&u.x), b = __half22float2(*(__half2*)&u.y);
            acc.x += a.x; acc.y += a.y; acc.z += b.x; acc.w += b.y;
        }
        const float cf = d_cntf[g];
        float4 b4 = *(const float4*)(bp + e * DIM + c * 4);
        acc.x = fmaf(cf, b4.x, acc.x);
        acc.y = fmaf(cf, b4.y, acc.y);
        acc.z = fmaf(cf, b4.z, acc.z);
        acc.w = fmaf(cf, b4.w, acc.w);
    }
    float vv[4] = {acc.x, acc.y, acc.z, acc.w};
    union { __nv_bfloat16 b[4]; uint2 u; } H, L;
    #pragma unroll
    for (int i = 0; i < 4; i++) {
        __nv_bfloat16 hb = __float2bfloat16(vv[i]);
        H.b[i] = hb;
        L.b[i] = __float2bfloat16(vv[i] - __bfloat162float(hb));
    }
    size_t o = (size_t)n * DIM + c * 4;
    *(uint2*)(d_ah + o) = H.u;
    *(uint2*)(d_al + o) = L.u;
}

// ---------------- warp-MMA GEMM: fused 3-product, 64x64 tile, 2 CTAs/SM ----
// MODE 0 (T)  : A={hh,hl} K=512, B=Bagg N=4096; epi: fp16 -> d_t
// MODE 1 (ZR) : A={a,h}  K=1024, B=Bzr N=1024; epi: z / rh
// MODE 2 (H)  : A={a,rh} K=1024, B=Bh  N=512;  epi: GRU combine
__device__ __forceinline__ const __nv_bfloat16* segA(int mode, bool lo, int seg) {
    if (mode == 0) return lo ? d_hl : d_hh;
    if (mode == 1) return seg ? (lo ? d_hl : d_hh) : (lo ? d_al : d_ah);
    return seg ? (lo ? d_rhl : d_rhh) : (lo ? d_al : d_ah);
}
__device__ __forceinline__ const __nv_bfloat16* segB(int mode, bool lo) {
    if (mode == 0) return lo ? d_Bagg_l : d_Bagg_h;
    if (mode == 1) return lo ? d_Bzr_l : d_Bzr_h;
    return lo ? d_Bh_l : d_Bh_h;
}

#define STAGES   3
#define STAGE_SZ 32768
#define SM_DYN   (STAGES * STAGE_SZ)   // 96 KB -> 2 CTAs/SM

template <int MODE>
__device__ __forceinline__ void load_tile_async(uint32_t stage_base, int t,
                                                int row0, int col0, int tid) {
    constexpr int BK = (MODE == 0) ? 512 : 1024;
    int seg = t >> 3, kti = t & 7;
    const char* Abh = (const char*)(segA(MODE, false, seg) + (size_t)row0 * 512 + kti * 64);
    const char* Abl = (const char*)(segA(MODE, true,  seg) + (size_t)row0 * 512 + kti * 64);
    const char* Bbh = (const char*)(segB(MODE, false) + (size_t)col0 * BK + seg * 512 + kti * 64);
    const char* Bbl = (const char*)(segB(MODE, true)  + (size_t)col0 * BK + seg * 512 + kti * 64);
    #pragma unroll
    for (int i = 0; i < 2; i++) {           // A: 64 rows x 128B (hi + lo)
        int cc = tid + (i << 8);
        int r = cc >> 3, kb = (cc & 7) << 4;
        int off = (r << 7) + kb;
        off ^= (off >> 3) & 0x70;
        cpa16(stage_base + off,        Abh + (size_t)r * 1024 + kb);
        cpa16(stage_base + 8192 + off, Abl + (size_t)r * 1024 + kb);
    }
    #pragma unroll
    for (int i = 0; i < 2; i++) {           // B: 64 rows x 128B (hi + lo)
        int cc = tid + (i << 8);
        int r = cc >> 3, kb = (cc & 7) << 4;
        int off = (r << 7) + kb;
        off ^= (off >> 3) & 0x70;
        cpa16(stage_base + 16384 + off, Bbh + (size_t)r * (BK * 2) + kb);
        cpa16(stage_base + 24576 + off, Bbl + (size_t)r * (BK * 2) + kb);
    }
}

template <int MODE>
__global__ void __launch_bounds__(256, 2)
mma_gemm(const float* __restrict__ bias1, const float* __restrict__ bias2,
         float* __restrict__ outF) {
    GDC_LAUNCH();
    extern __shared__ __align__(1024) char sm[];
    constexpr int KT = ((MODE == 0) ? 512 : 1024) / 64;
    const int tid = threadIdx.x, lane = tid & 31, warp = tid >> 5;
    const int wm = warp >> 1, wn = warp & 1;   // 4 x 2 warps, warp tile 16x32
    const int row0 = blockIdx.y * 64, col0 = blockIdx.x * 64;
    const uint32_t smb = (uint32_t)__cvta_generic_to_shared(sm);

    float acc[4][4];
    #pragma unroll
    for (int j = 0; j < 4; j++)
        #pragma unroll
        for (int q = 0; q < 4; q++) acc[j][q] = 0.0f;

    const uint32_t xmask = (uint32_t)(lane & 7) << 4;
    const int arow = lane & 15;
    const uint32_t ach0 = (uint32_t)(lane >> 4) << 4;
    const int brow = (lane & 7) + ((lane >> 4) << 3);
    const uint32_t bch0 = (uint32_t)((lane >> 3) & 1) << 4;

    GDC_WAIT();   // upstream results (h / a / rh) must be flushed before loads
    #pragma unroll
    for (int p = 0; p < STAGES - 1; p++) {
        load_tile_async<MODE>(smb + p * STAGE_SZ, p, row0, col0, tid);
        CPA_COMMIT();
    }

    int buf = 0;
    for (int t = 0; t < KT; t++) {
        CPA_WAIT1();
        __syncthreads();

        const int nt = t + STAGES - 1;
        if (nt < KT) {
            int nbuf = buf + STAGES - 1;
            if (nbuf >= STAGES) nbuf -= STAGES;
            load_tile_async<MODE>(smb + nbuf * STAGE_SZ, nt, row0, col0, tid);
        }
        CPA_COMMIT();

        const uint32_t S0 = smb + buf * STAGE_SZ;
        const uint32_t aAddr = S0 + (uint32_t)(wm * 16 + arow) * 128;
        const uint32_t bAddr0 = S0 + 16384 + (uint32_t)(wn * 32 + brow) * 128;
        const uint32_t bAddr1 = bAddr0 + 2048;

        #pragma unroll
        for (int k16 = 0; k16 < 4; k16++) {
            uint32_t ah[4], al[4], bh[2][4], bl[2][4];
            const uint32_t ak = (ach0 + k16 * 32) ^ xmask;
            const uint32_t bk = (bch0 + k16 * 32) ^ xmask;
            ldsm4(ah, aAddr + ak);
            ldsm4(al, aAddr + 8192 + ak);
            ldsm4(bh[0], bAddr0 + bk);
            ldsm4(bh[1], bAddr1 + bk);
            ldsm4(bl[0], bAddr0 + 8192 + bk);
            ldsm4(bl[1], bAddr1 + 8192 + bk);
            #pragma unroll
            for (int j = 0; j < 4; j++)
                mma16816(acc[j], ah, &bh[j >> 1][(j & 1) * 2]);
            #pragma unroll
            for (int j = 0; j < 4; j++)
                mma16816(acc[j], ah, &bl[j >> 1][(j & 1) * 2]);
            #pragma unroll
            for (int j = 0; j < 4; j++)
                mma16816(acc[j], al, &bh[j >> 1][(j & 1) * 2]);
        }

        if (++buf == STAGES) buf = 0;
    }

    // ---------------- epilogue ----------------
    #pragma unroll
    for (int hf = 0; hf < 2; hf++) {
        const int m = row0 + wm * 16 + (lane >> 2) + hf * 8;
        #pragma unroll
        for (int j = 0; j < 4; j++) {
            const int c = col0 + wn * 32 + j * 8 + (lane & 3) * 2;
            float v0 = acc[j][hf * 2 + 0];
            float v1 = acc[j][hf * 2 + 1];

            if (MODE == 0) {
                *(__half2*)(d_t + (size_t)m * 4096 + c) = __floats2half2_rn(v0, v1);
            } else if (MODE == 1) {
                if (c < DIM) {
                    v0 = 1.0f / (1.0f + __expf(-(v0 + __ldg(bias1 + c))));
                    v1 = 1.0f / (1.0f + __expf(-(v1 + __ldg(bias1 + c + 1))));
                    *(float2*)(d_z + (size_t)m * DIM + c) = make_float2(v0, v1);
                } else {
                    const int c2 = c - DIM;
                    size_t o = (size_t)m * DIM + c2;
                    float r0 = 1.0f / (1.0f + __expf(-(v0 + __ldg(bias2 + c2))));
                    float r1 = 1.0f / (1.0f + __expf(-(v1 + __ldg(bias2 + c2 + 1))));
                    float2 hv = *(const float2*)(d_h + o);
                    store_hilo2(d_rhh + o, d_rhl + o, r0 * hv.x, r1 * hv.y);
                }
            } else {
                size_t o = (size_t)m * DIM + c;
                float ht0 = tanhf(v0 + __ldg(bias1 + c));
                float ht1 = tanhf(v1 + __ldg(bias1 + c + 1));
                float2 hv = *(const float2*)(d_h + o);
                float2 zv = *(const float2*)(d_z + o);
                float n0 = hv.x + zv.x * (ht0 - hv.x);
                float n1 = hv.y + zv.y * (ht1 - hv.y);
                float* dst = outF ? outF : d_h;
                *(float2*)(dst + o) = make_float2(n0, n1);
                store_hilo2(d_hh + o, d_hl + o, n0, n1);
            }
        }
    }
}

// ---------------- PDL launch helper -----------------------------------------
template <typename... Args>
static void pdl_launch(void (*fn)(Args...), dim3 g, dim3 b, size_t smem, Args... args) {
    cudaLaunchConfig_t cfg = {};
    cfg.gridDim = g;
    cfg.blockDim = b;
    cfg.dynamicSmemBytes = smem;
    cfg.stream = 0;
    cudaLaunchAttribute at[1];
    at[0].id = cudaLaunchAttributeProgrammaticStreamSerialization;
    at[0].val.programmaticStreamSerializationAllowed = 1;
    cfg.attrs = at;
    cfg.numAttrs = 1;
    cudaLaunchKernelEx(&cfg, fn, args...);
}

// ---------------- launch ----------------------------------------------------
extern "C" void kernel_launch(void* const* d_in, const int* in_sizes, int n_in,
                              void* d_out, int out_size) {
    const float* adj = (const float*)d_in[0];
    const float* ann = (const float*)d_in[1];
    const float* Wp  = (const float*)d_in[2];
    const float* bp  = (const float*)d_in[3];
    const float* Wz  = (const float*)d_in[4];
    const float* Uz  = (const float*)d_in[5];
    const float* bz  = (const float*)d_in[6];
    const float* Wr  = (const float*)d_in[7];
    const float* Ur  = (const float*)d_in[8];
    const float* br  = (const float*)d_in[9];
    const float* Wh  = (const float*)d_in[10];
    const float* Uh  = (const float*)d_in[11];
    const float* bh  = (const float*)d_in[12];
    float* out = (float*)d_out;

    cudaFuncSetAttribute(mma_gemm<0>, cudaFuncAttributeMaxDynamicSharedMemorySize, SM_DYN);
    cudaFuncSetAttribute(mma_gemm<1>, cudaFuncAttributeMaxDynamicSharedMemorySize, SM_DYN);
    cudaFuncSetAttribute(mma_gemm<2>, cudaFuncAttributeMaxDynamicSharedMemorySize, SM_DYN);

    // side stream + events for prologue overlap (host objects leak; device-clean)
    cudaStream_t s1;
    cudaStreamCreateWithFlags(&s1, cudaStreamNonBlocking);
    cudaEvent_t evStart, evCsr;
    cudaEventCreateWithFlags(&evStart, cudaEventDisableTiming);
    cudaEventCreateWithFlags(&evCsr,   cudaEventDisableTiming);

    cudaEventRecord(evStart, 0);
    cudaStreamWaitEvent(s1, evStart, 0);
    csr_build<<<GROWS / 8, 256, 0, s1>>>(adj);     // DRAM-bound, independent
    cudaEventRecord(evCsr, s1);

    init_h<<<(NN * DIM) / 256, 256>>>(ann);
    packAll<<<dim3(16, 16, 14), dim3(32, 8)>>>(Wp, Wz, Uz, Wr, Ur, Wh, Uh);
    cudaStreamWaitEvent(0, evCsr, 0);

    dim3 gT(64, 32), gZr(16, 32), gH(8, 32);
    for (int step = 0; step < NSTEPS; step++) {
        pdl_launch(mma_gemm<0>, gT, dim3(256), (size_t)SM_DYN,
                   (const float*)nullptr, (const float*)nullptr, (float*)nullptr);
        pdl_launch(gather_acc, dim3(NN), dim3(128), (size_t)0, bp);
        pdl_launch(mma_gemm<1>, gZr, dim3(256), (size_t)SM_DYN,
                   bz, br, (float*)nullptr);
        pdl_launch(mma_gemm<2>, gH, dim3(256), (size_t)SM_DYN,
                   bh, (const float*)nullptr,
                   (step == NSTEPS - 1) ? out : (float*)nullptr);
    }
}

// round 17
// speedup vs baseline: 1.0202x; 1.0202x over previous
#include <cuda_runtime.h>
#include <cuda_bf16.h>
#include <cuda_fp16.h>
#include <cstdint>
#include <math.h>

#define NN      2048
#define DIM     512
#define EDGE    8
#define GROWS   (EDGE * NN)
#define SLOTS   128
#define NSTEPS  5

// ---------------- device scratch (no allocation allowed) -------------------
__device__ __align__(256) float d_h [NN * DIM];
__device__ __align__(256) float d_z [NN * DIM];
__device__ __align__(256) __half d_t [NN * 4096];   // t = h @ [W_0..W_7], fp16
__device__ __align__(256) __nv_bfloat16 d_hh [NN * DIM], d_hl [NN * DIM];
__device__ __align__(256) __nv_bfloat16 d_ah [NN * DIM], d_al [NN * DIM];
__device__ __align__(256) __nv_bfloat16 d_rhh[NN * DIM], d_rhl[NN * DIM];
__device__ __align__(256) __nv_bfloat16 d_Bagg_h[4096 * DIM], d_Bagg_l[4096 * DIM]; // [n=4096][k=512]
__device__ __align__(256) __nv_bfloat16 d_Bzr_h[1024 * 1024], d_Bzr_l[1024 * 1024]; // [1024][1024]
__device__ __align__(256) __nv_bfloat16 d_Bh_h [DIM * 1024],  d_Bh_l [DIM * 1024];  // [512][1024]
__device__ int   d_cnt   [GROWS];
__device__ float d_cntf  [GROWS];
__device__ int   d_colidx_pad[GROWS * SLOTS];

// ---------------- PDL + mma/ldmatrix/cp.async helpers ----------------------
#define GDC_LAUNCH() asm volatile("griddepcontrol.launch_dependents;")
#define GDC_WAIT()   asm volatile("griddepcontrol.wait;" ::: "memory")

__device__ __forceinline__ void ldsm4(uint32_t* r, uint32_t addr) {
    asm volatile("ldmatrix.sync.aligned.m8n8.x4.shared.b16 {%0,%1,%2,%3}, [%4];"
        : "=r"(r[0]), "=r"(r[1]), "=r"(r[2]), "=r"(r[3]) : "r"(addr));
}
__device__ __forceinline__ void mma16816(float* d, const uint32_t* a, const uint32_t* b) {
    asm volatile("mma.sync.aligned.m16n8k16.row.col.f32.bf16.bf16.f32 "
        "{%0,%1,%2,%3}, {%4,%5,%6,%7}, {%8,%9}, {%0,%1,%2,%3};"
        : "+f"(d[0]), "+f"(d[1]), "+f"(d[2]), "+f"(d[3])
        : "r"(a[0]), "r"(a[1]), "r"(a[2]), "r"(a[3]), "r"(b[0]), "r"(b[1]));
}
__device__ __forceinline__ void cpa16(uint32_t smaddr, const void* g) {
    asm volatile("cp.async.cg.shared.global [%0], [%1], 16;" :: "r"(smaddr), "l"(g));
}
#define CPA_COMMIT() asm volatile("cp.async.commit_group;")
#define CPA_WAIT1()  asm volatile("cp.async.wait_group 1;")

__device__ __forceinline__ void store_hilo2(__nv_bfloat16* ph, __nv_bfloat16* pl,
                                            float v0, float v1) {
    __nv_bfloat16 h0 = __float2bfloat16(v0);
    __nv_bfloat16 h1 = __float2bfloat16(v1);
    __nv_bfloat16 l0 = __float2bfloat16(v0 - __bfloat162float(h0));
    __nv_bfloat16 l1 = __float2bfloat16(v1 - __bfloat162float(h1));
    *(__nv_bfloat162*)ph = __nv_bfloat162(h0, h1);
    *(__nv_bfloat162*)pl = __nv_bfloat162(l0, l1);
}

// ---------------- single-pass padded CSR build ------------------------------
__global__ void csr_build(const float* __restrict__ adj) {
    int warp = (blockIdx.x * blockDim.x + threadIdx.x) >> 5;
    int lane = threadIdx.x & 31;
    if (warp >= GROWS) return;
    int e = warp >> 11, n = warp & 2047;
    const float* base = adj + (size_t)n * 16384 + (size_t)e * 2048;
    int* dst = d_colidx_pad + (size_t)warp * SLOTS;
    int w = 0;
    for (int i0 = 0; i0 < 2048; i0 += 32) {
        float v = base[i0 + lane];
        unsigned b = __ballot_sync(0xffffffffu, v != 0.0f);
        if (v != 0.0f) {
            int pos = w + __popc(b & ((1u << lane) - 1u));
            if (pos < SLOTS) dst[pos] = i0 + lane;
        }
        w += __popc(b);
    }
    if (lane == 0) {
        d_cnt[warp] = (w < SLOTS) ? w : SLOTS;
        d_cntf[warp] = (float)w;
    }
}

// ---------------- init h + hi/lo -------------------------------------------
__global__ void init_h(const float* __restrict__ ann) {
    int idx = blockIdx.x * blockDim.x + threadIdx.x;
    if (idx >= NN * DIM) return;
    int n = idx >> 9, d = idx & 511;
    float v = (d < 256) ? ann[n * 256 + d] : 0.0f;
    d_h[idx] = v;
    __nv_bfloat16 h = __float2bfloat16(v);
    d_hh[idx] = h;
    d_hl[idx] = __float2bfloat16(v - __bfloat162float(h));
}

// ---------------- weight transpose+pack (14 jobs, one launch) --------------
__global__ void packAll(const float* __restrict__ Wp, const float* __restrict__ Wz,
                        const float* __restrict__ Uz, const float* __restrict__ Wr,
                        const float* __restrict__ Ur, const float* __restrict__ Wh,
                        const float* __restrict__ Uh) {
    __shared__ float t[32][33];
    const int job = blockIdx.z;
    const float* src;
    __nv_bfloat16 *dh, *dl;
    int Kstride, nofs, kofs;
    if (job < 8) {
        src = Wp + (size_t)job * DIM * DIM;
        dh = d_Bagg_h; dl = d_Bagg_l; Kstride = 512; nofs = job * 512; kofs = 0;
    } else if (job < 12) {
        dh = d_Bzr_h; dl = d_Bzr_l; Kstride = 1024;
        if (job == 8)       { src = Wz; nofs = 0;   kofs = 0;   }
        else if (job == 9)  { src = Uz; nofs = 0;   kofs = 512; }
        else if (job == 10) { src = Wr; nofs = 512; kofs = 0;   }
        else                { src = Ur; nofs = 512; kofs = 512; }
    } else {
        dh = d_Bh_h; dl = d_Bh_l; Kstride = 1024;
        if (job == 12) { src = Wh; nofs = 0; kofs = 0;   }
        else           { src = Uh; nofs = 0; kofs = 512; }
    }
    int k0 = blockIdx.x * 32, n0 = blockIdx.y * 32;
    int tx = threadIdx.x, ty = threadIdx.y;   // (32,8)
    #pragma unroll
    for (int j = 0; j < 32; j += 8)
        t[ty + j][tx] = src[(size_t)(k0 + ty + j) * DIM + n0 + tx];
    __syncthreads();
    #pragma unroll
    for (int j = 0; j < 32; j += 8) {
        float v = t[tx][ty + j];
        size_t o = (size_t)(nofs + n0 + ty + j) * Kstride + kofs + k0 + tx;
        __nv_bfloat16 h = __float2bfloat16(v);
        dh[o] = h;
        dl[o] = __float2bfloat16(v - __bfloat162float(h));
    }
}

// ---------------- fused gather-accumulate: a[n] = sum_e sum_m t_e[m] + cnt*b
__global__ void __launch_bounds__(128)
gather_acc(const float* __restrict__ bp) {
    const int n = blockIdx.x;
    const int c = threadIdx.x;                 // 4 dims per thread
    GDC_WAIT();
    float4 acc = make_float4(0.f, 0.f, 0.f, 0.f);
    #pragma unroll 1
    for (int e = 0; e < EDGE; e++) {
        const int g = e * NN + n;
        const int* idxp = d_colidx_pad + (size_t)g * SLOTS;
        const int cnt = d_cnt[g];
        const __half* tb = d_t + e * 512 + c * 4;
        int j = 0;
        for (; j + 3 < cnt; j += 4) {
            int4 m4 = *(const int4*)(idxp + j);
            uint2 u0 = *(const uint2*)(tb + (size_t)m4.x * 4096);
            uint2 u1 = *(const uint2*)(tb + (size_t)m4.y * 4096);
            uint2 u2 = *(const uint2*)(tb + (size_t)m4.z * 4096);
            uint2 u3 = *(const uint2*)(tb + (size_t)m4.w * 4096);
            float2 a0 = __half22float2(*(__half2*)&u0.x), b0 = __half22float2(*(__half2*)&u0.y);
            float2 a1 = __half22float2(*(__half2*)&u1.x), b1 = __half22float2(*(__half2*)&u1.y);
            float2 a2 = __half22float2(*(__half2*)&u2.x), b2 = __half22float2(*(__half2*)&u2.y);
            float2 a3 = __half22float2(*(__half2*)&u3.x), b3 = __half22float2(*(__half2*)&u3.y);
            acc.x += (a0.x + a1.x) + (a2.x + a3.x);
            acc.y += (a0.y + a1.y) + (a2.y + a3.y);
            acc.z += (b0.x + b1.x) + (b2.x + b3.x);
            acc.w += (b0.y + b1.y) + (b2.y + b3.y);
        }
        for (; j < cnt; j++) {
            int m = __ldg(idxp + j);
            uint2 u = *(const uint2*)(tb + (size_t)m * 4096);
            float2 a = __half22float2(*(__half2*)&u.x), b = __half22float2(*(__half2*)&u.y);
            acc.x += a.x; acc.y += a.y; acc.z += b.x; acc.w += b.y;
        }
        const float cf = d_cntf[g];
        float4 b4 = *(const float4*)(bp + e * DIM + c * 4);
        acc.x = fmaf(cf, b4.x, acc.x);
        acc.y = fmaf(cf, b4.y, acc.y);
        acc.z = fmaf(cf, b4.z, acc.z);
        acc.w = fmaf(cf, b4.w, acc.w);
    }
    GDC_LAUNCH();   // late: dependents ramp during our store/drain window only
    float vv[4] = {acc.x, acc.y, acc.z, acc.w};
    union { __nv_bfloat16 b[4]; uint2 u; } H, L;
    #pragma unroll
    for (int i = 0; i < 4; i++) {
        __nv_bfloat16 hb = __float2bfloat16(vv[i]);
        H.b[i] = hb;
        L.b[i] = __float2bfloat16(vv[i] - __bfloat162float(hb));
    }
    size_t o = (size_t)n * DIM + c * 4;
    *(uint2*)(d_ah + o) = H.u;
    *(uint2*)(d_al + o) = L.u;
}

// ---------------- warp-MMA GEMM: fused 3-product, 64x64 tile, 2 CTAs/SM ----
// MODE 0 (T)  : A={hh,hl} K=512, B=Bagg N=4096; epi: fp16 -> d_t
// MODE 1 (ZR) : A={a,h}  K=1024, B=Bzr N=1024; epi: z / rh
// MODE 2 (H)  : A={a,rh} K=1024, B=Bh  N=512;  epi: GRU combine
__device__ __forceinline__ const __nv_bfloat16* segA(int mode, bool lo, int seg) {
    if (mode == 0) return lo ? d_hl : d_hh;
    if (mode == 1) return seg ? (lo ? d_hl : d_hh) : (lo ? d_al : d_ah);
    return seg ? (lo ? d_rhl : d_rhh) : (lo ? d_al : d_ah);
}
__device__ __forceinline__ const __nv_bfloat16* segB(int mode, bool lo) {
    if (mode == 0) return lo ? d_Bagg_l : d_Bagg_h;
    if (mode == 1) return lo ? d_Bzr_l : d_Bzr_h;
    return lo ? d_Bh_l : d_Bh_h;
}

#define STAGES   3
#define STAGE_SZ 32768
#define SM_DYN   (STAGES * STAGE_SZ)   // 96 KB -> 2 CTAs/SM

template <int MODE>
__device__ __forceinline__ void load_tile_async(uint32_t stage_base, int t,
                                                int row0, int col0, int tid) {
    constexpr int BK = (MODE == 0) ? 512 : 1024;
    int seg = t >> 3, kti = t & 7;
    const char* Abh = (const char*)(segA(MODE, false, seg) + (size_t)row0 * 512 + kti * 64);
    const char* Abl = (const char*)(segA(MODE, true,  seg) + (size_t)row0 * 512 + kti * 64);
    const char* Bbh = (const char*)(segB(MODE, false) + (size_t)col0 * BK + seg * 512 + kti * 64);
    const char* Bbl = (const char*)(segB(MODE, true)  + (size_t)col0 * BK + seg * 512 + kti * 64);
    #pragma unroll
    for (int i = 0; i < 2; i++) {           // A: 64 rows x 128B (hi + lo)
        int cc = tid + (i << 8);
        int r = cc >> 3, kb = (cc & 7) << 4;
        int off = (r << 7) + kb;
        off ^= (off >> 3) & 0x70;
        cpa16(stage_base + off,        Abh + (size_t)r * 1024 + kb);
        cpa16(stage_base + 8192 + off, Abl + (size_t)r * 1024 + kb);
    }
    #pragma unroll
    for (int i = 0; i < 2; i++) {           // B: 64 rows x 128B (hi + lo)
        int cc = tid + (i << 8);
        int r = cc >> 3, kb = (cc & 7) << 4;
        int off = (r << 7) + kb;
        off ^= (off >> 3) & 0x70;
        cpa16(stage_base + 16384 + off, Bbh + (size_t)r * (BK * 2) + kb);
        cpa16(stage_base + 24576 + off, Bbl + (size_t)r * (BK * 2) + kb);
    }
}

template <int MODE>
__global__ void __launch_bounds__(256, 2)
mma_gemm(const float* __restrict__ bias1, const float* __restrict__ bias2,
         float* __restrict__ outF) {
    extern __shared__ __align__(1024) char sm[];
    constexpr int KT = ((MODE == 0) ? 512 : 1024) / 64;
    const int tid = threadIdx.x, lane = tid & 31, warp = tid >> 5;
    const int wm = warp >> 1, wn = warp & 1;   // 4 x 2 warps, warp tile 16x32
    const int row0 = blockIdx.y * 64, col0 = blockIdx.x * 64;
    const uint32_t smb = (uint32_t)__cvta_generic_to_shared(sm);

    float acc[4][4];
    #pragma unroll
    for (int j = 0; j < 4; j++)
        #pragma unroll
        for (int q = 0; q < 4; q++) acc[j][q] = 0.0f;

    const uint32_t xmask = (uint32_t)(lane & 7) << 4;
    const int arow = lane & 15;
    const uint32_t ach0 = (uint32_t)(lane >> 4) << 4;
    const int brow = (lane & 7) + ((lane >> 4) << 3);
    const uint32_t bch0 = (uint32_t)((lane >> 3) & 1) << 4;

    GDC_WAIT();   // upstream results (h / a / rh) must be flushed before loads
    #pragma unroll
    for (int p = 0; p < STAGES - 1; p++) {
        load_tile_async<MODE>(smb + p * STAGE_SZ, p, row0, col0, tid);
        CPA_COMMIT();
    }

    int buf = 0;
    for (int t = 0; t < KT; t++) {
        CPA_WAIT1();
        __syncthreads();

        const int nt = t + STAGES - 1;
        if (nt < KT) {
            int nbuf = buf + STAGES - 1;
            if (nbuf >= STAGES) nbuf -= STAGES;
            load_tile_async<MODE>(smb + nbuf * STAGE_SZ, nt, row0, col0, tid);
        }
        CPA_COMMIT();

        const uint32_t S0 = smb + buf * STAGE_SZ;
        const uint32_t aAddr = S0 + (uint32_t)(wm * 16 + arow) * 128;
        const uint32_t bAddr0 = S0 + 16384 + (uint32_t)(wn * 32 + brow) * 128;
        const uint32_t bAddr1 = bAddr0 + 2048;

        #pragma unroll
        for (int k16 = 0; k16 < 4; k16++) {
            uint32_t ah[4], al[4], bh[2][4], bl[2][4];
            const uint32_t ak = (ach0 + k16 * 32) ^ xmask;
            const uint32_t bk = (bch0 + k16 * 32) ^ xmask;
            ldsm4(ah, aAddr + ak);
            ldsm4(al, aAddr + 8192 + ak);
            ldsm4(bh[0], bAddr0 + bk);
            ldsm4(bh[1], bAddr1 + bk);
            ldsm4(bl[0], bAddr0 + 8192 + bk);
            ldsm4(bl[1], bAddr1 + 8192 + bk);
            #pragma unroll
            for (int j = 0; j < 4; j++)
                mma16816(acc[j], ah, &bh[j >> 1][(j & 1) * 2]);
            #pragma unroll
            for (int j = 0; j < 4; j++)
                mma16816(acc[j], ah, &bl[j >> 1][(j & 1) * 2]);
            #pragma unroll
            for (int j = 0; j < 4; j++)
                mma16816(acc[j], al, &bh[j >> 1][(j & 1) * 2]);
        }

        if (++buf == STAGES) buf = 0;
    }

    GDC_LAUNCH();   // late: dependents ramp during epilogue + tail drain only

    // ---------------- epilogue ----------------
    #pragma unroll
    for (int hf = 0; hf < 2; hf++) {
        const int m = row0 + wm * 16 + (lane >> 2) + hf * 8;
        #pragma unroll
        for (int j = 0; j < 4; j++) {
            const int c = col0 + wn * 32 + j * 8 + (lane & 3) * 2;
            float v0 = acc[j][hf * 2 + 0];
            float v1 = acc[j][hf * 2 + 1];

            if (MODE == 0) {
                *(__half2*)(d_t + (size_t)m * 4096 + c) = __floats2half2_rn(v0, v1);
            } else if (MODE == 1) {
                if (c < DIM) {
                    v0 = 1.0f / (1.0f + __expf(-(v0 + __ldg(bias1 + c))));
                    v1 = 1.0f / (1.0f + __expf(-(v1 + __ldg(bias1 + c + 1))));
                    *(float2*)(d_z + (size_t)m * DIM + c) = make_float2(v0, v1);
                } else {
                    const int c2 = c - DIM;
                    size_t o = (size_t)m * DIM + c2;
                    float r0 = 1.0f / (1.0f + __expf(-(v0 + __ldg(bias2 + c2))));
                    float r1 = 1.0f / (1.0f + __expf(-(v1 + __ldg(bias2 + c2 + 1))));
                    float2 hv = *(const float2*)(d_h + o);
                    store_hilo2(d_rhh + o, d_rhl + o, r0 * hv.x, r1 * hv.y);
                }
            } else {
                size_t o = (size_t)m * DIM + c;
                float ht0 = tanhf(v0 + __ldg(bias1 + c));
                float ht1 = tanhf(v1 + __ldg(bias1 + c + 1));
                float2 hv = *(const float2*)(d_h + o);
                float2 zv = *(const float2*)(d_z + o);
                float n0 = hv.x + zv.x * (ht0 - hv.x);
                float n1 = hv.y + zv.y * (ht1 - hv.y);
                float* dst = outF ? outF : d_h;
                *(float2*)(dst + o) = make_float2(n0, n1);
                store_hilo2(d_hh + o, d_hl + o, n0, n1);
            }
        }
    }
}

// ---------------- PDL launch helper -----------------------------------------
template <typename... Args>
static void pdl_launch(void (*fn)(Args...), dim3 g, dim3 b, size_t smem, Args... args) {
    cudaLaunchConfig_t cfg = {};
    cfg.gridDim = g;
    cfg.blockDim = b;
    cfg.dynamicSmemBytes = smem;
    cfg.stream = 0;
    cudaLaunchAttribute at[1];
    at[0].id = cudaLaunchAttributeProgrammaticStreamSerialization;
    at[0].val.programmaticStreamSerializationAllowed = 1;
    cfg.attrs = at;
    cfg.numAttrs = 1;
    cudaLaunchKernelEx(&cfg, fn, args...);
}

// ---------------- launch ----------------------------------------------------
extern "C" void kernel_launch(void* const* d_in, const int* in_sizes, int n_in,
                              void* d_out, int out_size) {
    const float* adj = (const float*)d_in[0];
    const float* ann = (const float*)d_in[1];
    const float* Wp  = (const float*)d_in[2];
    const float* bp  = (const float*)d_in[3];
    const float* Wz  = (const float*)d_in[4];
    const float* Uz  = (const float*)d_in[5];
    const float* bz  = (const float*)d_in[6];
    const float* Wr  = (const float*)d_in[7];
    const float* Ur  = (const float*)d_in[8];
    const float* br  = (const float*)d_in[9];
    const float* Wh  = (const float*)d_in[10];
    const float* Uh  = (const float*)d_in[11];
    const float* bh  = (const float*)d_in[12];
    float* out = (float*)d_out;

    cudaFuncSetAttribute(mma_gemm<0>, cudaFuncAttributeMaxDynamicSharedMemorySize, SM_DYN);
    cudaFuncSetAttribute(mma_gemm<1>, cudaFuncAttributeMaxDynamicSharedMemorySize, SM_DYN);
    cudaFuncSetAttribute(mma_gemm<2>, cudaFuncAttributeMaxDynamicSharedMemorySize, SM_DYN);

    // side stream + events for prologue overlap (host objects leak; device-clean)
    cudaStream_t s1;
    cudaStreamCreateWithFlags(&s1, cudaStreamNonBlocking);
    cudaEvent_t evStart, evCsr;
    cudaEventCreateWithFlags(&evStart, cudaEventDisableTiming);
    cudaEventCreateWithFlags(&evCsr,   cudaEventDisableTiming);

    cudaEventRecord(evStart, 0);
    cudaStreamWaitEvent(s1, evStart, 0);
    csr_build<<<GROWS / 8, 256, 0, s1>>>(adj);     // DRAM-bound, independent
    cudaEventRecord(evCsr, s1);

    init_h<<<(NN * DIM) / 256, 256>>>(ann);
    packAll<<<dim3(16, 16, 14), dim3(32, 8)>>>(Wp, Wz, Uz, Wr, Ur, Wh, Uh);
    cudaStreamWaitEvent(0, evCsr, 0);

    dim3 gT(64, 32), gZr(16, 32), gH(8, 32);
    for (int step = 0; step < NSTEPS; step++) {
        pdl_launch(mma_gemm<0>, gT, dim3(256), (size_t)SM_DYN,
                   (const float*)nullptr, (const float*)nullptr, (float*)nullptr);
        pdl_launch(gather_acc, dim3(NN), dim3(128), (size_t)0, bp);
        pdl_launch(mma_gemm<1>, gZr, dim3(256), (size_t)SM_DYN,
                   bz, br, (float*)nullptr);
        pdl_launch(mma_gemm<2>, gH, dim3(256), (size_t)SM_DYN,
                   bh, (const float*)nullptr,
                   (step == NSTEPS - 1) ? out : (float*)nullptr);
    }
}